// round 14
// baseline (speedup 1.0000x reference)
#include <cuda_runtime.h>
#include <cstdint>

#define NT      256
#define NBLK    740     // one wave: 5 CTAs/SM x 148 SMs
#define STAGES  5
#define STAGE_F4 512    // 8KB per stage; 5 stages = 40KB smem in TMA flight per CTA

// Scratch: one partial per block + per-row bias sums + arrival counter.
__device__ float g_partials[NBLK];
__device__ float g_rowsums[128];
__device__ int   g_count = 0;

__device__ __forceinline__ uint32_t smem_u32(const void* p) {
    uint32_t a;
    asm("{ .reg .u64 t; cvta.to.shared.u64 t, %1; cvt.u32.u64 %0, t; }" : "=r"(a) : "l"(p));
    return a;
}

__device__ __forceinline__ void mbar_init(uint32_t mbar, uint32_t cnt) {
    asm volatile("mbarrier.init.shared.b64 [%0], %1;" :: "r"(mbar), "r"(cnt) : "memory");
}

__device__ __forceinline__ void mbar_expect_tx(uint32_t mbar, uint32_t bytes) {
    asm volatile("mbarrier.arrive.expect_tx.shared.b64 _, [%0], %1;"
                 :: "r"(mbar), "r"(bytes) : "memory");
}

__device__ __forceinline__ void mbar_wait(uint32_t mbar, int parity) {
    asm volatile(
        "{\n\t"
        ".reg .pred P;\n\t"
        "WL%=:\n\t"
        "mbarrier.try_wait.parity.acquire.cta.shared::cta.b64 P, [%0], %1, 0x989680;\n\t"
        "@P bra WD%=;\n\t"
        "bra WL%=;\n\t"
        "WD%=:\n\t"
        "}"
        :: "r"(mbar), "r"(parity) : "memory");
}

__device__ __forceinline__ void bulk_g2s(uint32_t dst, const void* src, uint32_t bytes,
                                         uint32_t mbar) {
    asm volatile(
        "cp.async.bulk.shared::cluster.global.mbarrier::complete_tx::bytes [%0], [%1], %2, [%3];"
        :: "r"(dst), "l"(src), "r"(bytes), "r"(mbar) : "memory");
}

__device__ __forceinline__ float block_reduce(float v, float* sdata) {
    int tid = threadIdx.x;
    #pragma unroll
    for (int off = 16; off > 0; off >>= 1)
        v += __shfl_down_sync(0xFFFFFFFFu, v, off);
    if ((tid & 31) == 0) sdata[tid >> 5] = v;
    __syncthreads();
    float r = 0.0f;
    if (tid < (NT / 32)) r = sdata[tid];
    if (tid < 32) {
        #pragma unroll
        for (int off = (NT / 64); off > 0; off >>= 1)
            r += __shfl_down_sync(0xFFFFFFFFu, r, off);
    }
    return r;  // valid in tid 0
}

__device__ __forceinline__ float sq4(float4 v, float s) {
    s = fmaf(v.x, v.x, s); s = fmaf(v.y, v.y, s);
    s = fmaf(v.z, v.z, s); s = fmaf(v.w, v.w, s);
    return s;
}

// Block partition boundaries: tensor t owns blocks [bs[t], bs[t+1])
__global__ __launch_bounds__(NT, 5)
void wr_tma_kernel(const float* __restrict__ wq, const float* __restrict__ wk,
                   const float* __restrict__ wv, const float* __restrict__ wo,
                   const float* __restrict__ w1, const float* __restrict__ w2,
                   const float* __restrict__ embed, const float* __restrict__ biases,
                   long n0, long n1, long n2, long n3, long n4, long n5, long n6,
                   int b1, int b2, int b3, int b4, int b5, int b6,
                   float* __restrict__ out)
{
    __shared__ __align__(128) float4 s_buf[STAGES * STAGE_F4];  // 40KB
    __shared__ __align__(8)  uint64_t s_mbar[STAGES];
    __shared__ float sdata[NT / 32];

    const float* ptrs[7] = {wq, wk, wv, wo, w1, w2, embed};
    const long ns[7]     = {n0, n1, n2, n3, n4, n5, n6};
    const int  bs[8]     = {0, b1, b2, b3, b4, b5, b6, NBLK};

    const int bid = blockIdx.x;
    const int tid = threadIdx.x;
    const uint32_t mb0 = smem_u32(s_mbar);
    const uint32_t sb0 = smem_u32(s_buf);

    if (tid == 0) {
        #pragma unroll
        for (int s = 0; s < STAGES; s++) mbar_init(mb0 + s * 8, 1);
    }
    __syncthreads();

    // which tensor / which contiguous chunk
    int t = 0;
    #pragma unroll
    for (int k = 1; k < 7; k++) if (bid >= bs[k]) t = k;
    const float4* __restrict__ p = (const float4*)ptrs[t];
    const long n4e   = ns[t] >> 2;
    const int  nblk  = bs[t + 1] - bs[t];
    const int  lb    = bid - bs[t];
    const long chunk = (n4e + nblk - 1) / nblk;
    long lo = (long)lb * chunk; if (lo > n4e) lo = n4e;
    long hi = lo + chunk;       if (hi > n4e) hi = n4e;
    const long total_f4 = hi - lo;
    const long nstages  = (total_f4 + STAGE_F4 - 1) / STAGE_F4;
    const char* gsrc = (const char*)(p + lo);

    // prologue: fill the pipeline
    if (tid == 0) {
        long pre = nstages < STAGES ? nstages : STAGES;
        for (long s = 0; s < pre; s++) {
            long off = s * STAGE_F4;
            long rem = total_f4 - off;
            uint32_t bytes = (uint32_t)((rem < STAGE_F4 ? rem : STAGE_F4) * 16);
            mbar_expect_tx(mb0 + (int)s * 8, bytes);
            bulk_g2s(sb0 + (uint32_t)(s * STAGE_F4 * 16), gsrc + off * 16, bytes,
                     mb0 + (int)s * 8);
        }
    }

    // mainloop
    float acc0 = 0.0f, acc1 = 0.0f;
    int slot = 0, ph = 0;
    for (long st = 0; st < nstages; st++) {
        mbar_wait(mb0 + slot * 8, ph);
        const long off  = st * STAGE_F4;
        const long remL = total_f4 - off;
        const int valid = (int)(remL < STAGE_F4 ? remL : STAGE_F4);
        const float4* sbp = s_buf + slot * STAGE_F4;
        if (tid < valid)      acc0 = sq4(sbp[tid], acc0);
        if (NT + tid < valid) acc1 = sq4(sbp[NT + tid], acc1);
        __syncthreads();  // all reads of this slot done before refill
        const long nst = st + STAGES;
        if (tid == 0 && nst < nstages) {
            long noff = nst * STAGE_F4;
            long nrem = total_f4 - noff;
            uint32_t bytes = (uint32_t)((nrem < STAGE_F4 ? nrem : STAGE_F4) * 16);
            mbar_expect_tx(mb0 + slot * 8, bytes);
            bulk_g2s(sb0 + (uint32_t)(slot * STAGE_F4 * 16), gsrc + noff * 16, bytes,
                     mb0 + slot * 8);
        }
        if (++slot == STAGES) { slot = 0; ph ^= 1; }
    }
    float s = acc0 + acc1;

    float r = block_reduce(s, sdata);
    if (tid == 0) g_partials[bid] = r;

    // Bias rows: blocks 0..127 each do one 8KB row via plain LDG
    if (bid < 128) {
        __syncthreads();  // sdata reuse
        const float4* __restrict__ pb = (const float4*)(biases) + (long)bid * 512;
        float sbv = 0.0f;
        for (int j = tid; j < 512; j += NT) sbv = sq4(__ldcs(pb + j), sbv);
        float rb = block_reduce(sbv, sdata);
        if (tid == 0) g_rowsums[bid] = rb;
    }

    // ---- last-block finalize (partials are L2-hot) ----
    __shared__ bool is_last;
    __threadfence();
    if (tid == 0) {
        int c = atomicAdd(&g_count, 1);
        is_last = (c == (int)gridDim.x - 1);
    }
    __syncthreads();
    if (!is_last) return;
    __threadfence();  // acquire side

    __shared__ float s_total;
    if (tid == 0) s_total = 0.0f;
    __syncthreads();

    #pragma unroll 1
    for (int tt = 0; tt < 7; tt++) {
        float sv = 0.0f;
        for (int j = bs[tt] + tid; j < bs[tt + 1]; j += NT) sv += g_partials[j];
        // scalar tail (n % 4): empty for these shapes, kept for safety
        if (tid == 0) {
            const float* pf = ptrs[tt];
            const long n = ns[tt];
            for (long j = (n >> 2) << 2; j < n; j++) sv = fmaf(pf[j], pf[j], sv);
        }
        float rv = block_reduce(sv, sdata);
        if (tid == 0) s_total += sqrtf(rv);
        __syncthreads();
    }

    float s2v = 0.0f;
    for (int j = tid; j < 128; j += NT) s2v += sqrtf(g_rowsums[j]);
    float rb2 = block_reduce(s2v, sdata);
    if (tid == 0) {
        out[0] = 0.0001f * ((s_total + rb2) / 135.0f);  // 7 mats + 128 rows
        g_count = 0;  // reset for next graph replay
    }
}

extern "C" void kernel_launch(void* const* d_in, const int* in_sizes, int n_in,
                              void* d_out, int out_size)
{
    const float* wq     = (const float*)d_in[0];
    const float* wk     = (const float*)d_in[1];
    const float* wv     = (const float*)d_in[2];
    const float* wo     = (const float*)d_in[3];
    const float* w1     = (const float*)d_in[4];
    const float* w2     = (const float*)d_in[5];
    const float* embed  = (const float*)d_in[6];
    const float* biases = (const float*)d_in[7];

    long n[7];
    long total = 0;
    for (int t = 0; t < 7; t++) { n[t] = (long)in_sizes[t]; total += n[t]; }

    // Proportional block partition over exactly one wave of NBLK blocks
    int bnd[8];
    bnd[0] = 0;
    long cum = 0;
    for (int t = 0; t < 7; t++) {
        cum += n[t];
        long b = (cum * NBLK + total / 2) / total;
        if (b <= bnd[t]) b = bnd[t] + 1;
        if (b > NBLK) b = NBLK;
        bnd[t + 1] = (int)b;
    }
    bnd[7] = NBLK;

    wr_tma_kernel<<<NBLK, NT>>>(wq, wk, wv, wo, w1, w2, embed, biases,
                                n[0], n[1], n[2], n[3], n[4], n[5], n[6],
                                bnd[1], bnd[2], bnd[3], bnd[4], bnd[5], bnd[6],
                                (float*)d_out);
}